// round 5
// baseline (speedup 1.0000x reference)
#include <cuda_runtime.h>
#include <math_constants.h>
#include <cstdint>

#define BS 128
#define M_CTR 16
#define BN_SCALE 0.9999950000374997f

// ---------------- scratch ----------------
__device__ int   g_fps[BS * M_CTR];
__device__ int   g_knn[BS * M_CTR * 2];
__device__ float g_GsT[65536 * 128];           // dense  C  [n=b*512+s*16+p][o]

// ---------------- helpers ----------------
__device__ __forceinline__ float gelu_exact(float x) {
    return 0.5f * x * (1.0f + erff(x * 0.70710678118654752f));
}
__device__ __forceinline__ float bn_gelu(float x, float g, float beta) {
    return gelu_exact(fmaf(g, x * BN_SCALE, beta));
}
__device__ __forceinline__ uint32_t f2tf(float f) {
    uint32_t o;
    asm("cvt.rna.tf32.f32 %0, %1;" : "=r"(o) : "f"(f));
    return o;
}
__device__ __forceinline__ void mma_tf32(float* d, const uint32_t* a, const uint32_t* b) {
    asm volatile(
        "mma.sync.aligned.m16n8k8.row.col.f32.tf32.tf32.f32 "
        "{%0,%1,%2,%3}, {%4,%5,%6,%7}, {%8,%9}, {%0,%1,%2,%3};\n"
        : "+f"(d[0]), "+f"(d[1]), "+f"(d[2]), "+f"(d[3])
        : "r"(a[0]), "r"(a[1]), "r"(a[2]), "r"(a[3]), "r"(b[0]), "r"(b[1]));
}

// ---------------------------------------------------------------------------
// FPS + kNN + coor_out.  One warp per batch. (exact f32, matches reference)
// ---------------------------------------------------------------------------
__global__ __launch_bounds__(32) void k_fps_knn(const float* __restrict__ coor,
                                                float* __restrict__ coor_out) {
    int b = blockIdx.x;
    int t = threadIdx.x;
    __shared__ float cs[32][33];
    __shared__ float sq[32];
    __shared__ int   fpsi[M_CTR];

    for (int c = 0; c < 32; c++) cs[t][c] = coor[(b * 32 + t) * 32 + c];
    float s = 0.f;
    for (int c = 0; c < 32; c++) { float v = cs[t][c]; s += v * v; }
    sq[t] = s;
    __syncthreads();

    float dist = CUDART_INF_F;
    int far = 0;
    for (int it = 0; it < M_CTR; it++) {
        if (t == 0) fpsi[it] = far;
        float d = 0.f;
        #pragma unroll
        for (int c = 0; c < 32; c++) { float df = cs[t][c] - cs[far][c]; d += df * df; }
        dist = fminf(dist, d);
        float bv = dist; int bi = t;
        #pragma unroll
        for (int o = 16; o > 0; o >>= 1) {
            float ov = __shfl_xor_sync(0xffffffffu, bv, o);
            int   oi = __shfl_xor_sync(0xffffffffu, bi, o);
            if (ov > bv || (ov == bv && oi < bi)) { bv = ov; bi = oi; }
        }
        far = bi;
    }
    __syncthreads();

    for (int m = 0; m < M_CTR; m++) {
        int r = fpsi[m];
        coor_out[(b * M_CTR + m) * 32 + t] = cs[r][t];
    }
    for (int m = 0; m < M_CTR; m++) {
        int ctr = fpsi[m];
        float dot = 0.f;
        #pragma unroll
        for (int c = 0; c < 32; c++) dot += cs[ctr][c] * cs[t][c];
        float d = sq[ctr] + sq[t] - 2.0f * dot;
        float bv = d; int bi = t;
        #pragma unroll
        for (int o = 16; o > 0; o >>= 1) {
            float ov = __shfl_xor_sync(0xffffffffu, bv, o);
            int   oi = __shfl_xor_sync(0xffffffffu, bi, o);
            if (ov < bv || (ov == bv && oi < bi)) { bv = ov; bi = oi; }
        }
        int i1 = bi;
        float d2 = (t == i1) ? CUDART_INF_F : d;
        float cv = d2; int ci = t;
        #pragma unroll
        for (int o = 16; o > 0; o >>= 1) {
            float ov = __shfl_xor_sync(0xffffffffu, cv, o);
            int   oi = __shfl_xor_sync(0xffffffffu, ci, o);
            if (ov < cv || (ov == cv && oi < ci)) { cv = ov; ci = oi; }
        }
        if (t == 0) {
            g_knn[(b * M_CTR + m) * 2 + 0] = i1;
            g_knn[(b * M_CTR + m) * 2 + 1] = ci;
        }
    }
    if (t < M_CTR) g_fps[b * M_CTR + t] = fpsi[t];
}

// ---------------------------------------------------------------------------
// Pipelined warp-mma tf32 GEMM. Block tile M=128, N=64; 8 warps (4Mx2N) of 32x32.
// Double-buffered smem, register prefetch, 1 sync per 16-K chunk.
// MODE 0: sparse (fused epilogue -> out_sparse)
// MODE 1: dense (K interleaved k=2c+par; float2 B loads) -> g_GsT[n][o]
// MODE 2: conv; B-fill computes d4 ON THE FLY from g_GsT (fused k_d4),
//         epilogue bias+BN+GELU -> out_dense
// ---------------------------------------------------------------------------
#define A_STR 20
#define B_STR 68

template <int MODE>
__global__ __launch_bounds__(256) void gemm_ws(const float* __restrict__ A0,
                                               const float* __restrict__ B0,
                                               const float* __restrict__ eb,
                                               const float* __restrict__ eg,
                                               const float* __restrict__ ebt,
                                               const float* __restrict__ db,
                                               const float* __restrict__ dg,
                                               const float* __restrict__ dbt,
                                               float* __restrict__ Cout) {
    __shared__ union {
        struct { uint32_t A[2][128 * A_STR]; uint32_t B[2][16 * B_STR]; } t;
        float Cs[128 * 65];
    } su;

    const int t = threadIdx.x;
    const int lane = t & 31;
    const int wid = t >> 5;
    const int g = lane >> 2, t4 = lane & 3;
    const int wm = wid & 3, wn = wid >> 2;

    // block mapping
    int b0 = 0, oT = 0;
    int bb = 0, s0 = 0, ng = 0, sg = 0;
    if (MODE == 0) {
        b0 = blockIdx.x * 2;
        oT = blockIdx.y * 64;
    } else if (MODE == 1) {
        bb = blockIdx.x >> 3; sg = blockIdx.x & 7; s0 = sg * 4;
    } else {
        bb = blockIdx.x >> 2; ng = blockIdx.x & 3;
    }

    const int NCH = (MODE == 2) ? 24 : 16;
    float ra[8], rb[4];

    auto loadA = [&](int ch) {
        int k0 = ch * 16;
        #pragma unroll
        for (int j = 0; j < 8; j++) {
            int idx = j * 256 + t;
            int kk = idx & 15, m = idx >> 4;
            if (MODE == 0) {
                int o = oT + (m & 63);
                ra[j] = __ldg(&A0[(size_t)o * 512 + ((m < 64) ? 0 : 256) + k0 + kk]);
            } else if (MODE == 1) {
                // K interleave: k = k0+kk -> c = k>>1, par = k&1
                ra[j] = __ldg(&A0[m * 256 + (kk & 1) * 128 + (k0 >> 1) + (kk >> 1)]);
            } else {
                int tap = k0 >> 7, i0 = k0 & 127;
                ra[j] = __ldg(&A0[m * 384 + (i0 + kk) * 3 + tap]);
            }
        }
    };
    auto loadB = [&](int ch) {
        int k0 = ch * 16;
        if (MODE == 0) {
            #pragma unroll
            for (int j = 0; j < 4; j++) {
                int idx = j * 256 + t;
                int n = idx & 63, kk = idx >> 6;
                int b = b0 + (n >> 5), s = n & 31;
                rb[j] = __ldg(&B0[((size_t)b * 256 + k0 + kk) * 32 + s]);
            }
        } else if (MODE == 1) {
            #pragma unroll
            for (int j = 0; j < 2; j++) {
                int idx = j * 256 + t;          // 512 items: n x kp
                int n = idx & 63, kp = idx >> 6; // kp 0..7
                int c = (k0 >> 1) + kp;
                int s = s0 + (n >> 4), p = n & 15;
                float2 v = *reinterpret_cast<const float2*>(
                    &B0[(((size_t)bb * 128 + c) * 32 + s) * 32 + 2 * p]);
                rb[2 * j] = v.x; rb[2 * j + 1] = v.y;
            }
        } else {
            // fused d4: value = bn_gelu(max over knn) computed from g_GsT
            int tap = k0 >> 7, i0 = k0 & 127;
            #pragma unroll
            for (int j = 0; j < 4; j++) {
                int idx = j * 256 + t;
                int kk = idx & 15, n = idx >> 4;
                int i = i0 + kk;
                int m = ng * 4 + (n >> 4), w = n & 15;
                int x = 2 * w - 1 + tap;
                float v = 0.f;
                if (x >= 0 && x < 32) {
                    int ctr = g_fps[bb * M_CTR + m];
                    float bbv = db[i], gg = dg[i], bt = dbt[i];
                    const float* Gb = g_GsT + (size_t)bb * 512 * 128;
                    if (x < 16) {
                        int i0n = g_knn[(bb * M_CTR + m) * 2 + 0];
                        int i1n = g_knn[(bb * M_CTR + m) * 2 + 1];
                        float gc = Gb[(size_t)(ctr * 16 + x) * 128 + i];
                        float x0 = Gb[(size_t)(i0n * 16 + x) * 128 + i] - gc + bbv;
                        float x1 = Gb[(size_t)(i1n * 16 + x) * 128 + i] - gc + bbv;
                        v = fmaxf(bn_gelu(x0, gg, bt), bn_gelu(x1, gg, bt));
                    } else {
                        float gc = Gb[(size_t)(ctr * 16 + (x - 16)) * 128 + i];
                        v = bn_gelu(gc + bbv, gg, bt);
                    }
                }
                rb[j] = v;
            }
        }
    };
    auto storeA = [&](int buf) {
        #pragma unroll
        for (int j = 0; j < 8; j++) {
            int idx = j * 256 + t;
            int kk = idx & 15, m = idx >> 4;
            su.t.A[buf][m * A_STR + kk] = f2tf(ra[j]);
        }
    };
    auto storeB = [&](int buf) {
        if (MODE == 0) {
            #pragma unroll
            for (int j = 0; j < 4; j++) {
                int idx = j * 256 + t;
                int n = idx & 63, kk = idx >> 6;
                su.t.B[buf][kk * B_STR + n] = f2tf(rb[j]);
            }
        } else if (MODE == 1) {
            #pragma unroll
            for (int j = 0; j < 2; j++) {
                int idx = j * 256 + t;
                int n = idx & 63, kp = idx >> 6;
                su.t.B[buf][(2 * kp) * B_STR + n]     = f2tf(rb[2 * j]);
                su.t.B[buf][(2 * kp + 1) * B_STR + n] = f2tf(rb[2 * j + 1]);
            }
        } else {
            #pragma unroll
            for (int j = 0; j < 4; j++) {
                int idx = j * 256 + t;
                int kk = idx & 15, n = idx >> 4;
                su.t.B[buf][kk * B_STR + n] = f2tf(rb[j]);
            }
        }
    };

    float d[2][4][4];
    #pragma unroll
    for (int mt = 0; mt < 2; mt++)
        #pragma unroll
        for (int nt = 0; nt < 4; nt++)
            #pragma unroll
            for (int e = 0; e < 4; e++) d[mt][nt][e] = 0.f;

    loadA(0); loadB(0);
    storeA(0); storeB(0);
    __syncthreads();

    for (int ch = 0; ch < NCH; ch++) {
        int buf = ch & 1;
        if (ch + 1 < NCH) { loadA(ch + 1); loadB(ch + 1); }
        const uint32_t* As = su.t.A[buf];
        const uint32_t* Bs = su.t.B[buf];
        #pragma unroll
        for (int ks = 0; ks < 2; ks++) {
            int ko = ks * 8;
            uint32_t a[2][4], bfr[4][2];
            #pragma unroll
            for (int mt = 0; mt < 2; mt++) {
                int r = wm * 32 + mt * 16 + g;
                a[mt][0] = As[r * A_STR + ko + t4];
                a[mt][1] = As[(r + 8) * A_STR + ko + t4];
                a[mt][2] = As[r * A_STR + ko + t4 + 4];
                a[mt][3] = As[(r + 8) * A_STR + ko + t4 + 4];
            }
            #pragma unroll
            for (int nt = 0; nt < 4; nt++) {
                int cn = wn * 32 + nt * 8 + g;
                bfr[nt][0] = Bs[(ko + t4) * B_STR + cn];
                bfr[nt][1] = Bs[(ko + t4 + 4) * B_STR + cn];
            }
            #pragma unroll
            for (int mt = 0; mt < 2; mt++)
                #pragma unroll
                for (int nt = 0; nt < 4; nt++)
                    mma_tf32(d[mt][nt], a[mt], bfr[nt]);
        }
        if (ch + 1 < NCH) { storeA(1 - buf); storeB(1 - buf); }
        __syncthreads();
    }

    if (MODE < 2) {
        #pragma unroll
        for (int mt = 0; mt < 2; mt++)
            #pragma unroll
            for (int nt = 0; nt < 4; nt++)
                #pragma unroll
                for (int e = 0; e < 4; e++) {
                    int m = wm * 32 + mt * 16 + g + ((e & 2) ? 8 : 0);
                    int n = wn * 32 + nt * 8 + 2 * t4 + (e & 1);
                    su.Cs[m * 65 + n] = d[mt][nt][e];
                }
        __syncthreads();
        if (MODE == 0) {
            #pragma unroll
            for (int j = 0; j < 8; j++) {
                int idx = j * 256 + t;
                int mm = idx & 15;
                int o_loc = (idx >> 4) & 63;
                int bl = idx >> 10;
                int b = b0 + bl;
                int cb = bl * 32;
                int ctr = g_fps[b * M_CTR + mm];
                int i0 = g_knn[(b * M_CTR + mm) * 2 + 0];
                int i1 = g_knn[(b * M_CTR + mm) * 2 + 1];
                float Ha_c = su.Cs[o_loc * 65 + cb + ctr];
                float Hc_c = su.Cs[(64 + o_loc) * 65 + cb + ctr];
                float Ha0  = su.Cs[o_loc * 65 + cb + i0];
                float Ha1  = su.Cs[o_loc * 65 + cb + i1];
                int o = oT + o_loc;
                float base = -Ha_c + Hc_c + eb[o];
                float gg = eg[o], bt = ebt[o];
                float r = fmaxf(bn_gelu(Ha0 + base, gg, bt), bn_gelu(Ha1 + base, gg, bt));
                Cout[(size_t)b * 4096 + o * 16 + mm] = r;
            }
        } else {
            #pragma unroll
            for (int j = 0; j < 32; j++) {
                int idx = j * 256 + t;
                int o = idx & 127, n = idx >> 7;
                g_GsT[((size_t)bb * 512 + sg * 64 + n) * 128 + o] = su.Cs[o * 65 + n];
            }
        }
    } else {
        #pragma unroll
        for (int mt = 0; mt < 2; mt++) {
            int o_lo = wm * 32 + mt * 16 + g;
            int o_hi = o_lo + 8;
            float b_lo = eb[o_lo], g_lo = eg[o_lo], t_lo = ebt[o_lo];
            float b_hi = eb[o_hi], g_hi = eg[o_hi], t_hi = ebt[o_hi];
            #pragma unroll
            for (int nt = 0; nt < 4; nt++) {
                int n = ng * 64 + wn * 32 + nt * 8 + 2 * t4;
                float2 v0, v1;
                v0.x = bn_gelu(d[mt][nt][0] + b_lo, g_lo, t_lo);
                v0.y = bn_gelu(d[mt][nt][1] + b_lo, g_lo, t_lo);
                v1.x = bn_gelu(d[mt][nt][2] + b_hi, g_hi, t_hi);
                v1.y = bn_gelu(d[mt][nt][3] + b_hi, g_hi, t_hi);
                *reinterpret_cast<float2*>(&Cout[((size_t)bb * 128 + o_lo) * 256 + n]) = v0;
                *reinterpret_cast<float2*>(&Cout[((size_t)bb * 128 + o_hi) * 256 + n]) = v1;
            }
        }
    }
}

// ---------------------------------------------------------------------------
extern "C" void kernel_launch(void* const* d_in, const int* in_sizes, int n_in,
                              void* d_out, int out_size) {
    const float* sparse_fea = (const float*)d_in[0];
    const float* dense_fea  = (const float*)d_in[1];
    const float* stk_coor   = (const float*)d_in[2];
    int base = 3;
    if (n_in >= 16 && in_sizes[3] == 1) base = 4;
    const float* sp_w    = (const float*)d_in[base + 0];
    const float* sp_b    = (const float*)d_in[base + 1];
    const float* sp_g    = (const float*)d_in[base + 2];
    const float* sp_beta = (const float*)d_in[base + 3];
    const float* dn_w    = (const float*)d_in[base + 4];
    const float* dn_b    = (const float*)d_in[base + 5];
    const float* dn_g    = (const float*)d_in[base + 6];
    const float* dn_beta = (const float*)d_in[base + 7];
    const float* ds_w    = (const float*)d_in[base + 8];
    const float* ds_b    = (const float*)d_in[base + 9];
    const float* ds_g    = (const float*)d_in[base + 10];
    const float* ds_beta = (const float*)d_in[base + 11];

    float* out = (float*)d_out;
    float* out_sparse = out;
    float* out_dense  = out + BS * 256 * M_CTR;
    float* out_coor   = out_dense + BS * 128 * M_CTR * 16;

    k_fps_knn<<<BS, 32>>>(stk_coor, out_coor);
    gemm_ws<0><<<dim3(64, 4), 256>>>(sp_w, sparse_fea, sp_b, sp_g, sp_beta,
                                     nullptr, nullptr, nullptr, out_sparse);
    gemm_ws<1><<<1024, 256>>>(dn_w, dense_fea, nullptr, nullptr, nullptr,
                              nullptr, nullptr, nullptr, nullptr);
    gemm_ws<2><<<512, 256>>>(ds_w, nullptr, ds_b, ds_g, ds_beta,
                             dn_b, dn_g, dn_beta, out_dense);
}

// round 6
// speedup vs baseline: 1.3070x; 1.3070x over previous
#include <cuda_runtime.h>
#include <math_constants.h>
#include <cstdint>

#define BS 128
#define M_CTR 16
#define BN_SCALE 0.9999950000374997f

// ---------------- scratch ----------------
__device__ int   g_fps[BS * M_CTR];
__device__ int   g_knn[BS * M_CTR * 2];
__device__ float g_GsT[65536 * 128];           // dense  C  [n=b*512+s*16+p][o]
__device__ float g_d4m[BS * 16 * 32 * 128];    // d4        [b][m][x][i]

// ---------------- helpers ----------------
__device__ __forceinline__ float gelu_exact(float x) {
    return 0.5f * x * (1.0f + erff(x * 0.70710678118654752f));
}
__device__ __forceinline__ float bn_gelu(float x, float g, float beta) {
    return gelu_exact(fmaf(g, x * BN_SCALE, beta));
}
__device__ __forceinline__ uint32_t f2tf(float f) {
    uint32_t o;
    asm("cvt.rna.tf32.f32 %0, %1;" : "=r"(o) : "f"(f));
    return o;
}
__device__ __forceinline__ void mma_tf32(float* d, const uint32_t* a, const uint32_t* b) {
    asm volatile(
        "mma.sync.aligned.m16n8k8.row.col.f32.tf32.tf32.f32 "
        "{%0,%1,%2,%3}, {%4,%5,%6,%7}, {%8,%9}, {%0,%1,%2,%3};\n"
        : "+f"(d[0]), "+f"(d[1]), "+f"(d[2]), "+f"(d[3])
        : "r"(a[0]), "r"(a[1]), "r"(a[2]), "r"(a[3]), "r"(b[0]), "r"(b[1]));
}

// ---------------------------------------------------------------------------
// FPS + kNN + coor_out.  One warp per batch. (exact f32, matches reference)
// ---------------------------------------------------------------------------
__global__ __launch_bounds__(32) void k_fps_knn(const float* __restrict__ coor,
                                                float* __restrict__ coor_out) {
    int b = blockIdx.x;
    int t = threadIdx.x;
    __shared__ float cs[32][33];
    __shared__ float sq[32];
    __shared__ int   fpsi[M_CTR];

    for (int c = 0; c < 32; c++) cs[t][c] = coor[(b * 32 + t) * 32 + c];
    float s = 0.f;
    for (int c = 0; c < 32; c++) { float v = cs[t][c]; s += v * v; }
    sq[t] = s;
    __syncthreads();

    float dist = CUDART_INF_F;
    int far = 0;
    for (int it = 0; it < M_CTR; it++) {
        if (t == 0) fpsi[it] = far;
        float d = 0.f;
        #pragma unroll
        for (int c = 0; c < 32; c++) { float df = cs[t][c] - cs[far][c]; d += df * df; }
        dist = fminf(dist, d);
        float bv = dist; int bi = t;
        #pragma unroll
        for (int o = 16; o > 0; o >>= 1) {
            float ov = __shfl_xor_sync(0xffffffffu, bv, o);
            int   oi = __shfl_xor_sync(0xffffffffu, bi, o);
            if (ov > bv || (ov == bv && oi < bi)) { bv = ov; bi = oi; }
        }
        far = bi;
    }
    __syncthreads();

    for (int m = 0; m < M_CTR; m++) {
        int r = fpsi[m];
        coor_out[(b * M_CTR + m) * 32 + t] = cs[r][t];
    }
    for (int m = 0; m < M_CTR; m++) {
        int ctr = fpsi[m];
        float dot = 0.f;
        #pragma unroll
        for (int c = 0; c < 32; c++) dot += cs[ctr][c] * cs[t][c];
        float d = sq[ctr] + sq[t] - 2.0f * dot;
        float bv = d; int bi = t;
        #pragma unroll
        for (int o = 16; o > 0; o >>= 1) {
            float ov = __shfl_xor_sync(0xffffffffu, bv, o);
            int   oi = __shfl_xor_sync(0xffffffffu, bi, o);
            if (ov < bv || (ov == bv && oi < bi)) { bv = ov; bi = oi; }
        }
        int i1 = bi;
        float d2 = (t == i1) ? CUDART_INF_F : d;
        float cv = d2; int ci = t;
        #pragma unroll
        for (int o = 16; o > 0; o >>= 1) {
            float ov = __shfl_xor_sync(0xffffffffu, cv, o);
            int   oi = __shfl_xor_sync(0xffffffffu, ci, o);
            if (ov < cv || (ov == cv && oi < ci)) { cv = ov; ci = oi; }
        }
        if (t == 0) {
            g_knn[(b * M_CTR + m) * 2 + 0] = i1;
            g_knn[(b * M_CTR + m) * 2 + 1] = ci;
        }
    }
    if (t < M_CTR) g_fps[b * M_CTR + t] = fpsi[t];
}

// ---------------------------------------------------------------------------
// Pipelined warp-mma tf32 GEMM, FRAGMENT-ORDER smem.
// Block tile M=128, N=64; 8 warps (4Mx2N) of 32x32 each.
// A frag layout: [tile(8)][ks(2)][lane(32)][slot(4)]  -> LDS.128 in mainloop
// B frag layout: [ntile(8)][ks(2)][lane(32)][slot(2)] -> LDS.64  in mainloop
// MODE 0: sparse (fused BN/GELU/max epilogue -> out_sparse)
// MODE 1: dense (K interleaved k=2c+par; float2 B loads) -> g_GsT[n][o]
// MODE 2: conv (B from g_d4m; epilogue bias+BN+GELU -> out_dense)
// ---------------------------------------------------------------------------
template <int MODE>
__global__ __launch_bounds__(256) void gemm_ws(const float* __restrict__ A0,
                                               const float* __restrict__ B0,
                                               const float* __restrict__ eb,
                                               const float* __restrict__ eg,
                                               const float* __restrict__ ebt,
                                               float* __restrict__ Cout) {
    __shared__ union {
        struct { uint32_t A[2][2048]; uint32_t B[2][1024]; } f;
        float Cs[128 * 65];
    } su;

    const int t = threadIdx.x;
    const int lane = t & 31;
    const int wid = t >> 5;
    const int g = lane >> 2, t4 = lane & 3;
    const int wm = wid & 3, wn = wid >> 2;

    // block mapping
    int b0 = 0, oT = 0;
    int bb = 0, s0 = 0, ng = 0, sg = 0;
    if (MODE == 0) {
        b0 = blockIdx.x * 2;
        oT = blockIdx.y * 64;
    } else if (MODE == 1) {
        bb = blockIdx.x >> 3; sg = blockIdx.x & 7; s0 = sg * 4;
    } else {
        bb = blockIdx.x >> 2; ng = blockIdx.x & 3;
    }

    const int NCH = (MODE == 2) ? 24 : 16;
    float ra[8], rb[4];

    auto loadA = [&](int ch) {
        int k0 = ch * 16;
        #pragma unroll
        for (int j = 0; j < 8; j++) {
            int idx = j * 256 + t;
            int kk = idx & 15, m = idx >> 4;
            if (MODE == 0) {
                int o = oT + (m & 63);
                ra[j] = __ldg(&A0[(size_t)o * 512 + ((m < 64) ? 0 : 256) + k0 + kk]);
            } else if (MODE == 1) {
                ra[j] = __ldg(&A0[m * 256 + (kk & 1) * 128 + (k0 >> 1) + (kk >> 1)]);
            } else {
                int tap = k0 >> 7, i0 = k0 & 127;
                ra[j] = __ldg(&A0[m * 384 + (i0 + kk) * 3 + tap]);
            }
        }
    };
    auto loadB = [&](int ch) {
        int k0 = ch * 16;
        if (MODE == 0) {
            #pragma unroll
            for (int j = 0; j < 4; j++) {
                int idx = j * 256 + t;
                int n = idx & 63, kk = idx >> 6;
                int b = b0 + (n >> 5), s = n & 31;
                rb[j] = __ldg(&B0[((size_t)b * 256 + k0 + kk) * 32 + s]);
            }
        } else if (MODE == 1) {
            #pragma unroll
            for (int j = 0; j < 2; j++) {
                int idx = j * 256 + t;
                int n = idx & 63, kp = idx >> 6;
                int c = (k0 >> 1) + kp;
                int s = s0 + (n >> 4), p = n & 15;
                float2 v = *reinterpret_cast<const float2*>(
                    &B0[(((size_t)bb * 128 + c) * 32 + s) * 32 + 2 * p]);
                rb[2 * j] = v.x; rb[2 * j + 1] = v.y;
            }
        } else {
            int tap = k0 >> 7, i0 = k0 & 127;
            #pragma unroll
            for (int j = 0; j < 4; j++) {
                int idx = j * 256 + t;
                int kk = idx & 15, n = idx >> 4;
                int m = ng * 4 + (n >> 4), w = n & 15;
                int x = 2 * w - 1 + tap;
                rb[j] = (x >= 0 && x < 32)
                            ? g_d4m[(((size_t)bb * 16 + m) * 32 + x) * 128 + i0 + kk]
                            : 0.f;
            }
        }
    };
    // fragment-order stores
    auto putA = [&](int buf, int m, int kk, float v) {
        int tile = m >> 4, r = m & 15;
        int ks = kk >> 3, c = kk & 7;
        int ln = (r & 7) * 4 + (c & 3);
        int slot = (r >> 3) + 2 * (c >> 2);
        su.f.A[buf][((tile * 2 + ks) << 7) + (ln << 2) + slot] = f2tf(v);
    };
    auto putB = [&](int buf, int kk, int n, float v) {
        int ks = kk >> 3, kr = kk & 7;
        int ntile = n >> 3;
        int ln = (n & 7) * 4 + (kr & 3);
        int slot = kr >> 2;
        su.f.B[buf][((ntile * 2 + ks) << 6) + (ln << 1) + slot] = f2tf(v);
    };
    auto storeA = [&](int buf) {
        #pragma unroll
        for (int j = 0; j < 8; j++) {
            int idx = j * 256 + t;
            putA(buf, idx >> 4, idx & 15, ra[j]);
        }
    };
    auto storeB = [&](int buf) {
        if (MODE == 1) {
            #pragma unroll
            for (int j = 0; j < 2; j++) {
                int idx = j * 256 + t;
                int n = idx & 63, kp = idx >> 6;
                putB(buf, 2 * kp,     n, rb[2 * j]);
                putB(buf, 2 * kp + 1, n, rb[2 * j + 1]);
            }
        } else {
            #pragma unroll
            for (int j = 0; j < 4; j++) {
                int idx = j * 256 + t;
                if (MODE == 0) putB(buf, idx >> 6, idx & 63, rb[j]);
                else           putB(buf, idx & 15, idx >> 4, rb[j]);
            }
        }
    };

    float d[2][4][4];
    #pragma unroll
    for (int mt = 0; mt < 2; mt++)
        #pragma unroll
        for (int nt = 0; nt < 4; nt++)
            #pragma unroll
            for (int e = 0; e < 4; e++) d[mt][nt][e] = 0.f;

    loadA(0); loadB(0);
    storeA(0); storeB(0);
    __syncthreads();

    for (int ch = 0; ch < NCH; ch++) {
        int buf = ch & 1;
        if (ch + 1 < NCH) { loadA(ch + 1); loadB(ch + 1); }
        const uint4* Af = reinterpret_cast<const uint4*>(su.f.A[buf]);
        const uint2* Bf = reinterpret_cast<const uint2*>(su.f.B[buf]);
        #pragma unroll
        for (int ks = 0; ks < 2; ks++) {
            uint32_t a[2][4], bfr[4][2];
            #pragma unroll
            for (int mt = 0; mt < 2; mt++) {
                uint4 av = Af[((2 * wm + mt) * 2 + ks) * 32 + lane];
                a[mt][0] = av.x; a[mt][1] = av.y; a[mt][2] = av.z; a[mt][3] = av.w;
            }
            #pragma unroll
            for (int nt = 0; nt < 4; nt++) {
                uint2 bv = Bf[((wn * 4 + nt) * 2 + ks) * 32 + lane];
                bfr[nt][0] = bv.x; bfr[nt][1] = bv.y;
            }
            #pragma unroll
            for (int mt = 0; mt < 2; mt++)
                #pragma unroll
                for (int nt = 0; nt < 4; nt++)
                    mma_tf32(d[mt][nt], a[mt], bfr[nt]);
        }
        if (ch + 1 < NCH) { storeA(1 - buf); storeB(1 - buf); }
        __syncthreads();
    }

    if (MODE < 2) {
        #pragma unroll
        for (int mt = 0; mt < 2; mt++)
            #pragma unroll
            for (int nt = 0; nt < 4; nt++)
                #pragma unroll
                for (int e = 0; e < 4; e++) {
                    int m = wm * 32 + mt * 16 + g + ((e & 2) ? 8 : 0);
                    int n = wn * 32 + nt * 8 + 2 * t4 + (e & 1);
                    su.Cs[m * 65 + n] = d[mt][nt][e];
                }
        __syncthreads();
        if (MODE == 0) {
            #pragma unroll
            for (int j = 0; j < 8; j++) {
                int idx = j * 256 + t;
                int mm = idx & 15;
                int o_loc = (idx >> 4) & 63;
                int bl = idx >> 10;
                int b = b0 + bl;
                int cb = bl * 32;
                int ctr = g_fps[b * M_CTR + mm];
                int i0 = g_knn[(b * M_CTR + mm) * 2 + 0];
                int i1 = g_knn[(b * M_CTR + mm) * 2 + 1];
                float Ha_c = su.Cs[o_loc * 65 + cb + ctr];
                float Hc_c = su.Cs[(64 + o_loc) * 65 + cb + ctr];
                float Ha0  = su.Cs[o_loc * 65 + cb + i0];
                float Ha1  = su.Cs[o_loc * 65 + cb + i1];
                int o = oT + o_loc;
                float base = -Ha_c + Hc_c + eb[o];
                float gg = eg[o], bt = ebt[o];
                float r = fmaxf(bn_gelu(Ha0 + base, gg, bt), bn_gelu(Ha1 + base, gg, bt));
                Cout[(size_t)b * 4096 + o * 16 + mm] = r;
            }
        } else {
            #pragma unroll
            for (int j = 0; j < 32; j++) {
                int idx = j * 256 + t;
                int o = idx & 127, n = idx >> 7;
                g_GsT[((size_t)bb * 512 + sg * 64 + n) * 128 + o] = su.Cs[o * 65 + n];
            }
        }
    } else {
        #pragma unroll
        for (int mt = 0; mt < 2; mt++) {
            int o_lo = wm * 32 + mt * 16 + g;
            int o_hi = o_lo + 8;
            float b_lo = eb[o_lo], g_lo = eg[o_lo], t_lo = ebt[o_lo];
            float b_hi = eb[o_hi], g_hi = eg[o_hi], t_hi = ebt[o_hi];
            #pragma unroll
            for (int nt = 0; nt < 4; nt++) {
                int n = ng * 64 + wn * 32 + nt * 8 + 2 * t4;
                float2 v0, v1;
                v0.x = bn_gelu(d[mt][nt][0] + b_lo, g_lo, t_lo);
                v0.y = bn_gelu(d[mt][nt][1] + b_lo, g_lo, t_lo);
                v1.x = bn_gelu(d[mt][nt][2] + b_hi, g_hi, t_hi);
                v1.y = bn_gelu(d[mt][nt][3] + b_hi, g_hi, t_hi);
                *reinterpret_cast<float2*>(&Cout[((size_t)bb * 128 + o_lo) * 256 + n]) = v0;
                *reinterpret_cast<float2*>(&Cout[((size_t)bb * 128 + o_hi) * 256 + n]) = v1;
            }
        }
    }
}

// ---------------------------------------------------------------------------
// d4 (vectorized x4 over i): g_d4m[b][m][x][i]
// ---------------------------------------------------------------------------
__global__ __launch_bounds__(256) void k_d4(const float* __restrict__ dn_b,
                                            const float* __restrict__ dn_g,
                                            const float* __restrict__ dn_beta) {
    int tid = blockIdx.x * 256 + threadIdx.x;
    int i = (tid & 31) * 4;
    int p = (tid >> 5) & 31;
    int m = (tid >> 10) & 15;
    int b = tid >> 14;
    int ctr = g_fps[b * M_CTR + m];
    float4 bb = *reinterpret_cast<const float4*>(&dn_b[i]);
    float4 gg = *reinterpret_cast<const float4*>(&dn_g[i]);
    float4 bt = *reinterpret_cast<const float4*>(&dn_beta[i]);
    const float* Gb = g_GsT + (size_t)b * 512 * 128;
    float4 v;
    if (p < 16) {
        int i0 = g_knn[(b * M_CTR + m) * 2 + 0];
        int i1 = g_knn[(b * M_CTR + m) * 2 + 1];
        float4 gc = *reinterpret_cast<const float4*>(&Gb[(size_t)(ctr * 16 + p) * 128 + i]);
        float4 x0 = *reinterpret_cast<const float4*>(&Gb[(size_t)(i0 * 16 + p) * 128 + i]);
        float4 x1 = *reinterpret_cast<const float4*>(&Gb[(size_t)(i1 * 16 + p) * 128 + i]);
        v.x = fmaxf(bn_gelu(x0.x - gc.x + bb.x, gg.x, bt.x), bn_gelu(x1.x - gc.x + bb.x, gg.x, bt.x));
        v.y = fmaxf(bn_gelu(x0.y - gc.y + bb.y, gg.y, bt.y), bn_gelu(x1.y - gc.y + bb.y, gg.y, bt.y));
        v.z = fmaxf(bn_gelu(x0.z - gc.z + bb.z, gg.z, bt.z), bn_gelu(x1.z - gc.z + bb.z, gg.z, bt.z));
        v.w = fmaxf(bn_gelu(x0.w - gc.w + bb.w, gg.w, bt.w), bn_gelu(x1.w - gc.w + bb.w, gg.w, bt.w));
    } else {
        float4 gc = *reinterpret_cast<const float4*>(&Gb[(size_t)(ctr * 16 + p - 16) * 128 + i]);
        v.x = bn_gelu(gc.x + bb.x, gg.x, bt.x);
        v.y = bn_gelu(gc.y + bb.y, gg.y, bt.y);
        v.z = bn_gelu(gc.z + bb.z, gg.z, bt.z);
        v.w = bn_gelu(gc.w + bb.w, gg.w, bt.w);
    }
    *reinterpret_cast<float4*>(&g_d4m[(((size_t)b * 16 + m) * 32 + p) * 128 + i]) = v;
}

// ---------------------------------------------------------------------------
extern "C" void kernel_launch(void* const* d_in, const int* in_sizes, int n_in,
                              void* d_out, int out_size) {
    const float* sparse_fea = (const float*)d_in[0];
    const float* dense_fea  = (const float*)d_in[1];
    const float* stk_coor   = (const float*)d_in[2];
    int base = 3;
    if (n_in >= 16 && in_sizes[3] == 1) base = 4;
    const float* sp_w    = (const float*)d_in[base + 0];
    const float* sp_b    = (const float*)d_in[base + 1];
    const float* sp_g    = (const float*)d_in[base + 2];
    const float* sp_beta = (const float*)d_in[base + 3];
    const float* dn_w    = (const float*)d_in[base + 4];
    const float* dn_b    = (const float*)d_in[base + 5];
    const float* dn_g    = (const float*)d_in[base + 6];
    const float* dn_beta = (const float*)d_in[base + 7];
    const float* ds_w    = (const float*)d_in[base + 8];
    const float* ds_b    = (const float*)d_in[base + 9];
    const float* ds_g    = (const float*)d_in[base + 10];
    const float* ds_beta = (const float*)d_in[base + 11];

    float* out = (float*)d_out;
    float* out_sparse = out;
    float* out_dense  = out + BS * 256 * M_CTR;
    float* out_coor   = out_dense + BS * 128 * M_CTR * 16;

    k_fps_knn<<<BS, 32>>>(stk_coor, out_coor);
    gemm_ws<0><<<dim3(64, 4), 256>>>(sp_w, sparse_fea, sp_b, sp_g, sp_beta, out_sparse);
    gemm_ws<1><<<1024, 256>>>(dn_w, dense_fea, nullptr, nullptr, nullptr, nullptr);
    k_d4<<<8192, 256>>>(dn_b, dn_g, dn_beta);
    gemm_ws<2><<<512, 256>>>(ds_w, nullptr, ds_b, ds_g, ds_beta, out_dense);
}

// round 7
// speedup vs baseline: 1.4065x; 1.0761x over previous
#include <cuda_runtime.h>
#include <math_constants.h>
#include <cstdint>

#define BS 128
#define M_CTR 16
#define BN_SCALE 0.9999950000374997f

// ---------------- scratch ----------------
__device__ int   g_fps[BS * M_CTR];
__device__ int   g_knn[BS * M_CTR * 2];
__device__ float g_GsT[65536 * 128];           // dense  C  [n=b*512+s*16+p][o]
__device__ float g_d4m[BS * 16 * 32 * 128];    // d4        [b][m][x][i]

// ---------------- helpers ----------------
__device__ __forceinline__ float gelu_exact(float x) {
    return 0.5f * x * (1.0f + erff(x * 0.70710678118654752f));
}
__device__ __forceinline__ float bn_gelu(float x, float g, float beta) {
    return gelu_exact(fmaf(g, x * BN_SCALE, beta));
}
__device__ __forceinline__ uint32_t f2tf(float f) {
    uint32_t o;
    asm("cvt.rna.tf32.f32 %0, %1;" : "=r"(o) : "f"(f));
    return o;
}
__device__ __forceinline__ void mma_tf32(float* d, const uint32_t* a, const uint32_t* b) {
    asm volatile(
        "mma.sync.aligned.m16n8k8.row.col.f32.tf32.tf32.f32 "
        "{%0,%1,%2,%3}, {%4,%5,%6,%7}, {%8,%9}, {%0,%1,%2,%3};\n"
        : "+f"(d[0]), "+f"(d[1]), "+f"(d[2]), "+f"(d[3])
        : "r"(a[0]), "r"(a[1]), "r"(a[2]), "r"(a[3]), "r"(b[0]), "r"(b[1]));
}

// ---------------------------------------------------------------------------
// FPS + kNN + coor_out.  One warp per batch. (exact f32, matches reference)
// ---------------------------------------------------------------------------
__global__ __launch_bounds__(32) void k_fps_knn(const float* __restrict__ coor,
                                                float* __restrict__ coor_out) {
    int b = blockIdx.x;
    int t = threadIdx.x;
    __shared__ float cs[32][33];
    __shared__ float sq[32];
    __shared__ int   fpsi[M_CTR];

    for (int c = 0; c < 32; c++) cs[t][c] = coor[(b * 32 + t) * 32 + c];
    float s = 0.f;
    for (int c = 0; c < 32; c++) { float v = cs[t][c]; s += v * v; }
    sq[t] = s;
    __syncthreads();

    float dist = CUDART_INF_F;
    int far = 0;
    for (int it = 0; it < M_CTR; it++) {
        if (t == 0) fpsi[it] = far;
        float d = 0.f;
        #pragma unroll
        for (int c = 0; c < 32; c++) { float df = cs[t][c] - cs[far][c]; d += df * df; }
        dist = fminf(dist, d);
        float bv = dist; int bi = t;
        #pragma unroll
        for (int o = 16; o > 0; o >>= 1) {
            float ov = __shfl_xor_sync(0xffffffffu, bv, o);
            int   oi = __shfl_xor_sync(0xffffffffu, bi, o);
            if (ov > bv || (ov == bv && oi < bi)) { bv = ov; bi = oi; }
        }
        far = bi;
    }
    __syncthreads();

    for (int m = 0; m < M_CTR; m++) {
        int r = fpsi[m];
        coor_out[(b * M_CTR + m) * 32 + t] = cs[r][t];
    }
    for (int m = 0; m < M_CTR; m++) {
        int ctr = fpsi[m];
        float dot = 0.f;
        #pragma unroll
        for (int c = 0; c < 32; c++) dot += cs[ctr][c] * cs[t][c];
        float d = sq[ctr] + sq[t] - 2.0f * dot;
        float bv = d; int bi = t;
        #pragma unroll
        for (int o = 16; o > 0; o >>= 1) {
            float ov = __shfl_xor_sync(0xffffffffu, bv, o);
            int   oi = __shfl_xor_sync(0xffffffffu, bi, o);
            if (ov < bv || (ov == bv && oi < bi)) { bv = ov; bi = oi; }
        }
        int i1 = bi;
        float d2 = (t == i1) ? CUDART_INF_F : d;
        float cv = d2; int ci = t;
        #pragma unroll
        for (int o = 16; o > 0; o >>= 1) {
            float ov = __shfl_xor_sync(0xffffffffu, cv, o);
            int   oi = __shfl_xor_sync(0xffffffffu, ci, o);
            if (ov < cv || (ov == cv && oi < ci)) { cv = ov; ci = oi; }
        }
        if (t == 0) {
            g_knn[(b * M_CTR + m) * 2 + 0] = i1;
            g_knn[(b * M_CTR + m) * 2 + 1] = ci;
        }
    }
    if (t < M_CTR) g_fps[b * M_CTR + t] = fpsi[t];
}

// ---------------------------------------------------------------------------
// Pipelined warp-mma tf32 GEMM, FRAGMENT-ORDER smem, KC=32 chunks.
// Block tile M=128, N=64; 8 warps (4Mx2N) of 32x32 each.
// A frag layout: [tile(8)][ks(4)][lane(32)][slot(4)]  -> LDS.128 in mainloop
// B frag layout: [ntile(8)][ks(4)][lane(32)][slot(2)] -> LDS.64  in mainloop
// MODE 0: sparse (fused BN/GELU/max epilogue -> out_sparse)      NCH=8
// MODE 1: dense (K interleaved k=2c+par) -> g_GsT[n][o]          NCH=8
// MODE 2: conv (B from g_d4m; epilogue bias+BN+GELU -> out)      NCH=12
// ---------------------------------------------------------------------------
template <int MODE>
__global__ __launch_bounds__(256) void gemm_ws(const float* __restrict__ A0,
                                               const float* __restrict__ B0,
                                               const float* __restrict__ eb,
                                               const float* __restrict__ eg,
                                               const float* __restrict__ ebt,
                                               float* __restrict__ Cout) {
    __shared__ union {
        struct { uint32_t A[2][4096]; uint32_t B[2][2048]; } f;
        float Cs[128 * 65];
    } su;

    const int t = threadIdx.x;
    const int lane = t & 31;
    const int wid = t >> 5;
    const int g = lane >> 2, t4 = lane & 3;
    const int wm = wid & 3, wn = wid >> 2;

    // block mapping
    int b0 = 0, oT = 0;
    int bb = 0, s0 = 0, ng = 0, sg = 0;
    if (MODE == 0) {
        b0 = blockIdx.x * 2;
        oT = blockIdx.y * 64;
    } else if (MODE == 1) {
        bb = blockIdx.x >> 3; sg = blockIdx.x & 7; s0 = sg * 4;
    } else {
        bb = blockIdx.x >> 2; ng = blockIdx.x & 3;
    }

    const int NCH = (MODE == 2) ? 12 : 8;
    float ra[16], rb[8];

    auto loadA = [&](int ch) {
        int k0 = ch * 32;
        #pragma unroll
        for (int j = 0; j < 16; j++) {
            int idx = j * 256 + t;
            int kk = idx & 31, m = idx >> 5;
            if (MODE == 0) {
                int o = oT + (m & 63);
                ra[j] = __ldg(&A0[(size_t)o * 512 + ((m < 64) ? 0 : 256) + k0 + kk]);
            } else if (MODE == 1) {
                ra[j] = __ldg(&A0[m * 256 + (kk & 1) * 128 + (k0 >> 1) + (kk >> 1)]);
            } else {
                int tap = k0 >> 7, i0 = k0 & 127;
                ra[j] = __ldg(&A0[m * 384 + (i0 + kk) * 3 + tap]);
            }
        }
    };
    auto loadB = [&](int ch) {
        int k0 = ch * 32;
        if (MODE == 0) {
            #pragma unroll
            for (int j = 0; j < 8; j++) {
                int idx = j * 256 + t;
                int n = idx & 63, kk = idx >> 6;
                int b = b0 + (n >> 5), s = n & 31;
                rb[j] = __ldg(&B0[((size_t)b * 256 + k0 + kk) * 32 + s]);
            }
        } else if (MODE == 1) {
            #pragma unroll
            for (int j = 0; j < 4; j++) {
                int idx = j * 256 + t;
                int n = idx & 63, kp = idx >> 6;      // kp 0..15
                int c = (k0 >> 1) + kp;
                int s = s0 + (n >> 4), p = n & 15;
                float2 v = *reinterpret_cast<const float2*>(
                    &B0[(((size_t)bb * 128 + c) * 32 + s) * 32 + 2 * p]);
                rb[2 * j] = v.x; rb[2 * j + 1] = v.y;
            }
        } else {
            int tap = k0 >> 7, i0 = k0 & 127;
            #pragma unroll
            for (int j = 0; j < 8; j++) {
                int idx = j * 256 + t;
                int kk = idx & 31, n = idx >> 5;
                int m = ng * 4 + (n >> 4), w = n & 15;
                int x = 2 * w - 1 + tap;
                rb[j] = (x >= 0 && x < 32)
                            ? g_d4m[(((size_t)bb * 16 + m) * 32 + x) * 128 + i0 + kk]
                            : 0.f;
            }
        }
    };
    // fragment-order stores (ks now 0..3)
    auto putA = [&](int buf, int m, int kk, float v) {
        int tile = m >> 4, r = m & 15;
        int ks = kk >> 3, c = kk & 7;
        int ln = (r & 7) * 4 + (c & 3);
        int slot = (r >> 3) + 2 * (c >> 2);
        su.f.A[buf][((tile * 4 + ks) << 7) + (ln << 2) + slot] = f2tf(v);
    };
    auto putB = [&](int buf, int kk, int n, float v) {
        int ks = kk >> 3, kr = kk & 7;
        int ntile = n >> 3;
        int ln = (n & 7) * 4 + (kr & 3);
        int slot = kr >> 2;
        su.f.B[buf][((ntile * 4 + ks) << 6) + (ln << 1) + slot] = f2tf(v);
    };
    auto storeA = [&](int buf) {
        #pragma unroll
        for (int j = 0; j < 16; j++) {
            int idx = j * 256 + t;
            putA(buf, idx >> 5, idx & 31, ra[j]);
        }
    };
    auto storeB = [&](int buf) {
        if (MODE == 1) {
            #pragma unroll
            for (int j = 0; j < 4; j++) {
                int idx = j * 256 + t;
                int n = idx & 63, kp = idx >> 6;
                putB(buf, 2 * kp,     n, rb[2 * j]);
                putB(buf, 2 * kp + 1, n, rb[2 * j + 1]);
            }
        } else {
            #pragma unroll
            for (int j = 0; j < 8; j++) {
                int idx = j * 256 + t;
                if (MODE == 0) putB(buf, idx >> 6, idx & 63, rb[j]);
                else           putB(buf, idx & 31, idx >> 5, rb[j]);
            }
        }
    };

    float d[2][4][4];
    #pragma unroll
    for (int mt = 0; mt < 2; mt++)
        #pragma unroll
        for (int nt = 0; nt < 4; nt++)
            #pragma unroll
            for (int e = 0; e < 4; e++) d[mt][nt][e] = 0.f;

    loadA(0); loadB(0);
    storeA(0); storeB(0);
    __syncthreads();

    for (int ch = 0; ch < NCH; ch++) {
        int buf = ch & 1;
        if (ch + 1 < NCH) { loadA(ch + 1); loadB(ch + 1); }
        const uint4* Af = reinterpret_cast<const uint4*>(su.f.A[buf]);
        const uint2* Bf = reinterpret_cast<const uint2*>(su.f.B[buf]);
        #pragma unroll
        for (int ks = 0; ks < 4; ks++) {
            uint32_t a[2][4], bfr[4][2];
            #pragma unroll
            for (int mt = 0; mt < 2; mt++) {
                uint4 av = Af[((2 * wm + mt) * 4 + ks) * 32 + lane];
                a[mt][0] = av.x; a[mt][1] = av.y; a[mt][2] = av.z; a[mt][3] = av.w;
            }
            #pragma unroll
            for (int nt = 0; nt < 4; nt++) {
                uint2 bv = Bf[((wn * 4 + nt) * 4 + ks) * 32 + lane];
                bfr[nt][0] = bv.x; bfr[nt][1] = bv.y;
            }
            #pragma unroll
            for (int mt = 0; mt < 2; mt++)
                #pragma unroll
                for (int nt = 0; nt < 4; nt++)
                    mma_tf32(d[mt][nt], a[mt], bfr[nt]);
        }
        if (ch + 1 < NCH) { storeA(1 - buf); storeB(1 - buf); }
        __syncthreads();
    }

    if (MODE < 2) {
        #pragma unroll
        for (int mt = 0; mt < 2; mt++)
            #pragma unroll
            for (int nt = 0; nt < 4; nt++)
                #pragma unroll
                for (int e = 0; e < 4; e++) {
                    int m = wm * 32 + mt * 16 + g + ((e & 2) ? 8 : 0);
                    int n = wn * 32 + nt * 8 + 2 * t4 + (e & 1);
                    su.Cs[m * 65 + n] = d[mt][nt][e];
                }
        __syncthreads();
        if (MODE == 0) {
            #pragma unroll
            for (int j = 0; j < 8; j++) {
                int idx = j * 256 + t;
                int mm = idx & 15;
                int o_loc = (idx >> 4) & 63;
                int bl = idx >> 10;
                int b = b0 + bl;
                int cb = bl * 32;
                int ctr = g_fps[b * M_CTR + mm];
                int i0 = g_knn[(b * M_CTR + mm) * 2 + 0];
                int i1 = g_knn[(b * M_CTR + mm) * 2 + 1];
                float Ha_c = su.Cs[o_loc * 65 + cb + ctr];
                float Hc_c = su.Cs[(64 + o_loc) * 65 + cb + ctr];
                float Ha0  = su.Cs[o_loc * 65 + cb + i0];
                float Ha1  = su.Cs[o_loc * 65 + cb + i1];
                int o = oT + o_loc;
                float base = -Ha_c + Hc_c + eb[o];
                float gg = eg[o], bt = ebt[o];
                float r = fmaxf(bn_gelu(Ha0 + base, gg, bt), bn_gelu(Ha1 + base, gg, bt));
                Cout[(size_t)b * 4096 + o * 16 + mm] = r;
            }
        } else {
            // vectorized: 8 x STG.128 per thread
            #pragma unroll
            for (int j = 0; j < 8; j++) {
                int idx = j * 256 + t;
                int o4 = (idx & 31) * 4, n = idx >> 5;
                float4 v;
                v.x = su.Cs[(o4 + 0) * 65 + n];
                v.y = su.Cs[(o4 + 1) * 65 + n];
                v.z = su.Cs[(o4 + 2) * 65 + n];
                v.w = su.Cs[(o4 + 3) * 65 + n];
                *reinterpret_cast<float4*>(
                    &g_GsT[((size_t)bb * 512 + sg * 64 + n) * 128 + o4]) = v;
            }
        }
    } else {
        #pragma unroll
        for (int mt = 0; mt < 2; mt++) {
            int o_lo = wm * 32 + mt * 16 + g;
            int o_hi = o_lo + 8;
            float b_lo = eb[o_lo], g_lo = eg[o_lo], t_lo = ebt[o_lo];
            float b_hi = eb[o_hi], g_hi = eg[o_hi], t_hi = ebt[o_hi];
            #pragma unroll
            for (int nt = 0; nt < 4; nt++) {
                int n = ng * 64 + wn * 32 + nt * 8 + 2 * t4;
                float2 v0, v1;
                v0.x = bn_gelu(d[mt][nt][0] + b_lo, g_lo, t_lo);
                v0.y = bn_gelu(d[mt][nt][1] + b_lo, g_lo, t_lo);
                v1.x = bn_gelu(d[mt][nt][2] + b_hi, g_hi, t_hi);
                v1.y = bn_gelu(d[mt][nt][3] + b_hi, g_hi, t_hi);
                *reinterpret_cast<float2*>(&Cout[((size_t)bb * 128 + o_lo) * 256 + n]) = v0;
                *reinterpret_cast<float2*>(&Cout[((size_t)bb * 128 + o_hi) * 256 + n]) = v1;
            }
        }
    }
}

// ---------------------------------------------------------------------------
// d4 paired-p: thread handles x=p' and x=p'+16 (shared gc load + params).
// ---------------------------------------------------------------------------
__global__ __launch_bounds__(256) void k_d4(const float* __restrict__ dn_b,
                                            const float* __restrict__ dn_g,
                                            const float* __restrict__ dn_beta) {
    int tid = blockIdx.x * 256 + threadIdx.x;
    int i = (tid & 31) * 4;
    int p = (tid >> 5) & 15;
    int m = (tid >> 9) & 15;
    int b = tid >> 13;
    int ctr = g_fps[b * M_CTR + m];
    int i0 = g_knn[(b * M_CTR + m) * 2 + 0];
    int i1 = g_knn[(b * M_CTR + m) * 2 + 1];
    float4 bb = *reinterpret_cast<const float4*>(&dn_b[i]);
    float4 gg = *reinterpret_cast<const float4*>(&dn_g[i]);
    float4 bt = *reinterpret_cast<const float4*>(&dn_beta[i]);
    const float* Gb = g_GsT + (size_t)b * 512 * 128;
    float4 gc = *reinterpret_cast<const float4*>(&Gb[(size_t)(ctr * 16 + p) * 128 + i]);
    float4 x0 = *reinterpret_cast<const float4*>(&Gb[(size_t)(i0 * 16 + p) * 128 + i]);
    float4 x1 = *reinterpret_cast<const float4*>(&Gb[(size_t)(i1 * 16 + p) * 128 + i]);
    float4 va, vb2;
    va.x = fmaxf(bn_gelu(x0.x - gc.x + bb.x, gg.x, bt.x), bn_gelu(x1.x - gc.x + bb.x, gg.x, bt.x));
    va.y = fmaxf(bn_gelu(x0.y - gc.y + bb.y, gg.y, bt.y), bn_gelu(x1.y - gc.y + bb.y, gg.y, bt.y));
    va.z = fmaxf(bn_gelu(x0.z - gc.z + bb.z, gg.z, bt.z), bn_gelu(x1.z - gc.z + bb.z, gg.z, bt.z));
    va.w = fmaxf(bn_gelu(x0.w - gc.w + bb.w, gg.w, bt.w), bn_gelu(x1.w - gc.w + bb.w, gg.w, bt.w));
    vb2.x = bn_gelu(gc.x + bb.x, gg.x, bt.x);
    vb2.y = bn_gelu(gc.y + bb.y, gg.y, bt.y);
    vb2.z = bn_gelu(gc.z + bb.z, gg.z, bt.z);
    vb2.w = bn_gelu(gc.w + bb.w, gg.w, bt.w);
    float* outp = g_d4m + (((size_t)b * 16 + m) * 32 + p) * 128 + i;
    *reinterpret_cast<float4*>(outp) = va;
    *reinterpret_cast<float4*>(outp + 16 * 128) = vb2;
}

// ---------------------------------------------------------------------------
extern "C" void kernel_launch(void* const* d_in, const int* in_sizes, int n_in,
                              void* d_out, int out_size) {
    const float* sparse_fea = (const float*)d_in[0];
    const float* dense_fea  = (const float*)d_in[1];
    const float* stk_coor   = (const float*)d_in[2];
    int base = 3;
    if (n_in >= 16 && in_sizes[3] == 1) base = 4;
    const float* sp_w    = (const float*)d_in[base + 0];
    const float* sp_b    = (const float*)d_in[base + 1];
    const float* sp_g    = (const float*)d_in[base + 2];
    const float* sp_beta = (const float*)d_in[base + 3];
    const float* dn_w    = (const float*)d_in[base + 4];
    const float* dn_b    = (const float*)d_in[base + 5];
    const float* dn_g    = (const float*)d_in[base + 6];
    const float* dn_beta = (const float*)d_in[base + 7];
    const float* ds_w    = (const float*)d_in[base + 8];
    const float* ds_b    = (const float*)d_in[base + 9];
    const float* ds_g    = (const float*)d_in[base + 10];
    const float* ds_beta = (const float*)d_in[base + 11];

    float* out = (float*)d_out;
    float* out_sparse = out;
    float* out_dense  = out + BS * 256 * M_CTR;
    float* out_coor   = out_dense + BS * 128 * M_CTR * 16;

    k_fps_knn<<<BS, 32>>>(stk_coor, out_coor);
    gemm_ws<0><<<dim3(64, 4), 256>>>(sp_w, sparse_fea, sp_b, sp_g, sp_beta, out_sparse);
    gemm_ws<1><<<1024, 256>>>(dn_w, dense_fea, nullptr, nullptr, nullptr, nullptr);
    k_d4<<<4096, 256>>>(dn_b, dn_g, dn_beta);
    gemm_ws<2><<<512, 256>>>(ds_w, nullptr, ds_b, ds_g, ds_beta, out_dense);
}

// round 8
// speedup vs baseline: 1.7572x; 1.2493x over previous
#include <cuda_runtime.h>
#include <math_constants.h>
#include <cstdint>

#define BS 128
#define M_CTR 16
#define BN_SCALE 0.9999950000374997f

// ---------------- scratch ----------------
__device__ int   g_fps[BS * M_CTR];
__device__ int   g_knn[BS * M_CTR * 2];
__device__ float g_GsT[65536 * 128];           // dense  C  [n=b*512+s*16+p][o]
__device__ float g_d4m[BS * 16 * 32 * 128];    // d4        [b][m][x][i]

// ---------------- helpers ----------------
__device__ __forceinline__ float gelu_exact(float x) {
    return 0.5f * x * (1.0f + erff(x * 0.70710678118654752f));
}
__device__ __forceinline__ float bn_gelu(float x, float g, float beta) {
    return gelu_exact(fmaf(g, x * BN_SCALE, beta));
}
__device__ __forceinline__ uint32_t f2tf(float f) {
    uint32_t o;
    asm("cvt.rna.tf32.f32 %0, %1;" : "=r"(o) : "f"(f));
    return o;
}
__device__ __forceinline__ void mma_tf32(float* d, const uint32_t* a, const uint32_t* b) {
    asm volatile(
        "mma.sync.aligned.m16n8k8.row.col.f32.tf32.tf32.f32 "
        "{%0,%1,%2,%3}, {%4,%5,%6,%7}, {%8,%9}, {%0,%1,%2,%3};\n"
        : "+f"(d[0]), "+f"(d[1]), "+f"(d[2]), "+f"(d[3])
        : "r"(a[0]), "r"(a[1]), "r"(a[2]), "r"(a[3]), "r"(b[0]), "r"(b[1]));
}

// ---------------------------------------------------------------------------
// FPS + kNN + coor_out.  One warp per batch. (exact f32, matches reference)
// ---------------------------------------------------------------------------
__global__ __launch_bounds__(32) void k_fps_knn(const float* __restrict__ coor,
                                                float* __restrict__ coor_out) {
    int b = blockIdx.x;
    int t = threadIdx.x;
    __shared__ float cs[32][33];
    __shared__ float sq[32];
    __shared__ int   fpsi[M_CTR];

    for (int c = 0; c < 32; c++) cs[t][c] = coor[(b * 32 + t) * 32 + c];
    float s = 0.f;
    for (int c = 0; c < 32; c++) { float v = cs[t][c]; s += v * v; }
    sq[t] = s;
    __syncthreads();

    float dist = CUDART_INF_F;
    int far = 0;
    for (int it = 0; it < M_CTR; it++) {
        if (t == 0) fpsi[it] = far;
        float d = 0.f;
        #pragma unroll
        for (int c = 0; c < 32; c++) { float df = cs[t][c] - cs[far][c]; d += df * df; }
        dist = fminf(dist, d);
        float bv = dist; int bi = t;
        #pragma unroll
        for (int o = 16; o > 0; o >>= 1) {
            float ov = __shfl_xor_sync(0xffffffffu, bv, o);
            int   oi = __shfl_xor_sync(0xffffffffu, bi, o);
            if (ov > bv || (ov == bv && oi < bi)) { bv = ov; bi = oi; }
        }
        far = bi;
    }
    __syncthreads();

    for (int m = 0; m < M_CTR; m++) {
        int r = fpsi[m];
        coor_out[(b * M_CTR + m) * 32 + t] = cs[r][t];
    }
    for (int m = 0; m < M_CTR; m++) {
        int ctr = fpsi[m];
        float dot = 0.f;
        #pragma unroll
        for (int c = 0; c < 32; c++) dot += cs[ctr][c] * cs[t][c];
        float d = sq[ctr] + sq[t] - 2.0f * dot;
        float bv = d; int bi = t;
        #pragma unroll
        for (int o = 16; o > 0; o >>= 1) {
            float ov = __shfl_xor_sync(0xffffffffu, bv, o);
            int   oi = __shfl_xor_sync(0xffffffffu, bi, o);
            if (ov < bv || (ov == bv && oi < bi)) { bv = ov; bi = oi; }
        }
        int i1 = bi;
        float d2 = (t == i1) ? CUDART_INF_F : d;
        float cv = d2; int ci = t;
        #pragma unroll
        for (int o = 16; o > 0; o >>= 1) {
            float ov = __shfl_xor_sync(0xffffffffu, cv, o);
            int   oi = __shfl_xor_sync(0xffffffffu, ci, o);
            if (ov < cv || (ov == cv && oi < ci)) { cv = ov; ci = oi; }
        }
        if (t == 0) {
            g_knn[(b * M_CTR + m) * 2 + 0] = i1;
            g_knn[(b * M_CTR + m) * 2 + 1] = ci;
        }
    }
    if (t < M_CTR) g_fps[b * M_CTR + t] = fpsi[t];
}

// ---------------------------------------------------------------------------
// Sparse GEMM (unchanged from R7, MODE 0 only): 128x64 tile, KC=32,
// fragment-order smem, fused BN/GELU/max epilogue -> out_sparse.
// ---------------------------------------------------------------------------
__global__ __launch_bounds__(256) void gemm_sparse(const float* __restrict__ A0,
                                                   const float* __restrict__ B0,
                                                   const float* __restrict__ eb,
                                                   const float* __restrict__ eg,
                                                   const float* __restrict__ ebt,
                                                   float* __restrict__ Cout) {
    __shared__ union {
        struct { uint32_t A[2][4096]; uint32_t B[2][2048]; } f;
        float Cs[128 * 65];
    } su;

    const int t = threadIdx.x;
    const int lane = t & 31;
    const int wid = t >> 5;
    const int g = lane >> 2, t4 = lane & 3;
    const int wm = wid & 3, wn = wid >> 2;

    int b0 = blockIdx.x * 2;
    int oT = blockIdx.y * 64;

    const int NCH = 8;
    float ra[16], rb[8];

    auto loadA = [&](int ch) {
        int k0 = ch * 32;
        #pragma unroll
        for (int j = 0; j < 16; j++) {
            int idx = j * 256 + t;
            int kk = idx & 31, m = idx >> 5;
            int o = oT + (m & 63);
            ra[j] = __ldg(&A0[(size_t)o * 512 + ((m < 64) ? 0 : 256) + k0 + kk]);
        }
    };
    auto loadB = [&](int ch) {
        int k0 = ch * 32;
        #pragma unroll
        for (int j = 0; j < 8; j++) {
            int idx = j * 256 + t;
            int n = idx & 63, kk = idx >> 6;
            int b = b0 + (n >> 5), s = n & 31;
            rb[j] = __ldg(&B0[((size_t)b * 256 + k0 + kk) * 32 + s]);
        }
    };
    auto putA = [&](int buf, int m, int kk, float v) {
        int tile = m >> 4, r = m & 15;
        int ks = kk >> 3, c = kk & 7;
        int ln = (r & 7) * 4 + (c & 3);
        int slot = (r >> 3) + 2 * (c >> 2);
        su.f.A[buf][((tile * 4 + ks) << 7) + (ln << 2) + slot] = f2tf(v);
    };
    auto putB = [&](int buf, int kk, int n, float v) {
        int ks = kk >> 3, kr = kk & 7;
        int ntile = n >> 3;
        int ln = (n & 7) * 4 + (kr & 3);
        int slot = kr >> 2;
        su.f.B[buf][((ntile * 4 + ks) << 6) + (ln << 1) + slot] = f2tf(v);
    };
    auto storeA = [&](int buf) {
        #pragma unroll
        for (int j = 0; j < 16; j++) {
            int idx = j * 256 + t;
            putA(buf, idx >> 5, idx & 31, ra[j]);
        }
    };
    auto storeB = [&](int buf) {
        #pragma unroll
        for (int j = 0; j < 8; j++) {
            int idx = j * 256 + t;
            putB(buf, idx >> 6, idx & 63, rb[j]);
        }
    };

    float d[2][4][4];
    #pragma unroll
    for (int mt = 0; mt < 2; mt++)
        #pragma unroll
        for (int nt = 0; nt < 4; nt++)
            #pragma unroll
            for (int e = 0; e < 4; e++) d[mt][nt][e] = 0.f;

    loadA(0); loadB(0);
    storeA(0); storeB(0);
    __syncthreads();

    for (int ch = 0; ch < NCH; ch++) {
        int buf = ch & 1;
        if (ch + 1 < NCH) { loadA(ch + 1); loadB(ch + 1); }
        const uint4* Af = reinterpret_cast<const uint4*>(su.f.A[buf]);
        const uint2* Bf = reinterpret_cast<const uint2*>(su.f.B[buf]);
        #pragma unroll
        for (int ks = 0; ks < 4; ks++) {
            uint32_t a[2][4], bfr[4][2];
            #pragma unroll
            for (int mt = 0; mt < 2; mt++) {
                uint4 av = Af[((2 * wm + mt) * 4 + ks) * 32 + lane];
                a[mt][0] = av.x; a[mt][1] = av.y; a[mt][2] = av.z; a[mt][3] = av.w;
            }
            #pragma unroll
            for (int nt = 0; nt < 4; nt++) {
                uint2 bv = Bf[((wn * 4 + nt) * 4 + ks) * 32 + lane];
                bfr[nt][0] = bv.x; bfr[nt][1] = bv.y;
            }
            #pragma unroll
            for (int mt = 0; mt < 2; mt++)
                #pragma unroll
                for (int nt = 0; nt < 4; nt++)
                    mma_tf32(d[mt][nt], a[mt], bfr[nt]);
        }
        if (ch + 1 < NCH) { storeA(1 - buf); storeB(1 - buf); }
        __syncthreads();
    }

    #pragma unroll
    for (int mt = 0; mt < 2; mt++)
        #pragma unroll
        for (int nt = 0; nt < 4; nt++)
            #pragma unroll
            for (int e = 0; e < 4; e++) {
                int m = wm * 32 + mt * 16 + g + ((e & 2) ? 8 : 0);
                int n = wn * 32 + nt * 8 + 2 * t4 + (e & 1);
                su.Cs[m * 65 + n] = d[mt][nt][e];
            }
    __syncthreads();
    #pragma unroll
    for (int j = 0; j < 8; j++) {
        int idx = j * 256 + t;
        int mm = idx & 15;
        int o_loc = (idx >> 4) & 63;
        int bl = idx >> 10;
        int b = b0 + bl;
        int cb = bl * 32;
        int ctr = g_fps[b * M_CTR + mm];
        int i0 = g_knn[(b * M_CTR + mm) * 2 + 0];
        int i1 = g_knn[(b * M_CTR + mm) * 2 + 1];
        float Ha_c = su.Cs[o_loc * 65 + cb + ctr];
        float Hc_c = su.Cs[(64 + o_loc) * 65 + cb + ctr];
        float Ha0  = su.Cs[o_loc * 65 + cb + i0];
        float Ha1  = su.Cs[o_loc * 65 + cb + i1];
        int o = oT + o_loc;
        float base = -Ha_c + Hc_c + eb[o];
        float gg = eg[o], bt = ebt[o];
        float r = fmaxf(bn_gelu(Ha0 + base, gg, bt), bn_gelu(Ha1 + base, gg, bt));
        Cout[(size_t)b * 4096 + o * 16 + mm] = r;
    }
}

// ---------------------------------------------------------------------------
// BIG GEMM: 128x128 block tile, 8 warps (2M x 4N), warp tile 64x32, KC=16,
// fragment-order double-buffered smem (dynamic).
// MODE 1: dense  (K interleaved k=2c+par) -> g_GsT[n][o]   NCH=16
// MODE 2: conv   (B gathered from g_d4m)  -> bn_gelu->out  NCH=24
// ---------------------------------------------------------------------------
template <int MODE>
__global__ __launch_bounds__(256, 2) void gemm_big(const float* __restrict__ A0,
                                                   const float* __restrict__ B0,
                                                   const float* __restrict__ eb,
                                                   const float* __restrict__ eg,
                                                   const float* __restrict__ ebt,
                                                   float* __restrict__ Cout) {
    extern __shared__ uint32_t dsm[];
    uint32_t* Abuf = dsm;          // [2][2048]
    uint32_t* Bbuf = dsm + 4096;   // [2][2048]
    float*    Cs   = reinterpret_cast<float*>(dsm);   // MODE 1 epilogue [n][132]

    const int t = threadIdx.x;
    const int lane = t & 31;
    const int wid = t >> 5;
    const int g = lane >> 2, t4 = lane & 3;
    const int wm = wid & 1, wn = wid >> 1;

    int bb, s0 = 0, ng = 0, sg = 0;
    if (MODE == 1) { bb = blockIdx.x >> 2; sg = blockIdx.x & 3; s0 = sg * 8; }
    else           { bb = blockIdx.x >> 1; ng = blockIdx.x & 1; }

    const int NCH = (MODE == 1) ? 16 : 24;
    float ra[8], rb[8];

    auto loadA = [&](int ch) {
        int k0 = ch * 16;
        #pragma unroll
        for (int j = 0; j < 8; j++) {
            int idx = j * 256 + t;
            int kk = idx & 15, m = idx >> 4;
            if (MODE == 1) {
                ra[j] = __ldg(&A0[m * 256 + (kk & 1) * 128 + (k0 >> 1) + (kk >> 1)]);
            } else {
                int tap = k0 >> 7, i0 = k0 & 127;
                ra[j] = __ldg(&A0[m * 384 + (i0 + kk) * 3 + tap]);
            }
        }
    };
    auto loadB = [&](int ch) {
        int k0 = ch * 16;
        if (MODE == 1) {
            #pragma unroll
            for (int j = 0; j < 4; j++) {
                int idx = j * 256 + t;
                int n = idx & 127, kp = idx >> 7;     // kp 0..7
                int c = (k0 >> 1) + kp;
                int s = s0 + (n >> 4), p = n & 15;
                float2 v = *reinterpret_cast<const float2*>(
                    &B0[(((size_t)bb * 128 + c) * 32 + s) * 32 + 2 * p]);
                rb[2 * j] = v.x; rb[2 * j + 1] = v.y;
            }
        } else {
            int tap = k0 >> 7, i0 = k0 & 127;
            #pragma unroll
            for (int j = 0; j < 8; j++) {
                int idx = j * 256 + t;
                int kk = idx & 15, n = idx >> 4;      // n 0..127
                int m = ng * 8 + (n >> 4), w = n & 15;
                int x = 2 * w - 1 + tap;
                rb[j] = (x >= 0 && x < 32)
                            ? g_d4m[(((size_t)bb * 16 + m) * 32 + x) * 128 + i0 + kk]
                            : 0.f;
            }
        }
    };
    auto putA = [&](int buf, int m, int kk, float v) {
        int tile = m >> 4, r = m & 15;
        int ks = kk >> 3, c = kk & 7;
        int ln = (r & 7) * 4 + (c & 3);
        int slot = (r >> 3) + 2 * (c >> 2);
        Abuf[buf * 2048 + ((tile * 2 + ks) << 7) + (ln << 2) + slot] = f2tf(v);
    };
    auto putB = [&](int buf, int kk, int n, float v) {
        int ks = kk >> 3, kr = kk & 7;
        int ntile = n >> 3;                            // 0..15
        int ln = (n & 7) * 4 + (kr & 3);
        int slot = kr >> 2;
        Bbuf[buf * 2048 + ((ntile * 2 + ks) << 6) + (ln << 1) + slot] = f2tf(v);
    };
    auto storeA = [&](int buf) {
        #pragma unroll
        for (int j = 0; j < 8; j++) {
            int idx = j * 256 + t;
            putA(buf, idx >> 4, idx & 15, ra[j]);
        }
    };
    auto storeB = [&](int buf) {
        if (MODE == 1) {
            #pragma unroll
            for (int j = 0; j < 4; j++) {
                int idx = j * 256 + t;
                int n = idx & 127, kp = idx >> 7;
                putB(buf, 2 * kp,     n, rb[2 * j]);
                putB(buf, 2 * kp + 1, n, rb[2 * j + 1]);
            }
        } else {
            #pragma unroll
            for (int j = 0; j < 8; j++) {
                int idx = j * 256 + t;
                putB(buf, idx & 15, idx >> 4, rb[j]);
            }
        }
    };

    float d[4][4][4];
    #pragma unroll
    for (int mt = 0; mt < 4; mt++)
        #pragma unroll
        for (int nt = 0; nt < 4; nt++)
            #pragma unroll
            for (int e = 0; e < 4; e++) d[mt][nt][e] = 0.f;

    loadA(0); loadB(0);
    storeA(0); storeB(0);
    __syncthreads();

    for (int ch = 0; ch < NCH; ch++) {
        int buf = ch & 1;
        if (ch + 1 < NCH) { loadA(ch + 1); loadB(ch + 1); }
        const uint4* Af = reinterpret_cast<const uint4*>(Abuf + buf * 2048);
        const uint2* Bf = reinterpret_cast<const uint2*>(Bbuf + buf * 2048);
        #pragma unroll
        for (int ks = 0; ks < 2; ks++) {
            uint32_t a[4][4], bfr[4][2];
            #pragma unroll
            for (int mt = 0; mt < 4; mt++) {
                uint4 av = Af[((wm * 4 + mt) * 2 + ks) * 32 + lane];
                a[mt][0] = av.x; a[mt][1] = av.y; a[mt][2] = av.z; a[mt][3] = av.w;
            }
            #pragma unroll
            for (int nt = 0; nt < 4; nt++) {
                uint2 bv = Bf[((wn * 4 + nt) * 2 + ks) * 32 + lane];
                bfr[nt][0] = bv.x; bfr[nt][1] = bv.y;
            }
            #pragma unroll
            for (int mt = 0; mt < 4; mt++)
                #pragma unroll
                for (int nt = 0; nt < 4; nt++)
                    mma_tf32(d[mt][nt], a[mt], bfr[nt]);
        }
        if (ch + 1 < NCH) { storeA(1 - buf); storeB(1 - buf); }
        __syncthreads();
    }

    if (MODE == 1) {
        // transpose through smem: Cs[n][m] stride 132 (conflict-free both phases)
        #pragma unroll
        for (int mt = 0; mt < 4; mt++)
            #pragma unroll
            for (int nt = 0; nt < 4; nt++)
                #pragma unroll
                for (int e = 0; e < 4; e++) {
                    int m = wm * 64 + mt * 16 + g + ((e & 2) ? 8 : 0);
                    int n = wn * 32 + nt * 8 + 2 * t4 + (e & 1);
                    Cs[n * 132 + m] = d[mt][nt][e];
                }
        __syncthreads();
        #pragma unroll
        for (int j = 0; j < 16; j++) {
            int idx = j * 256 + t;
            int o4 = (idx & 31) * 4, n = idx >> 5;    // n 0..127
            float4 v = *reinterpret_cast<const float4*>(&Cs[n * 132 + o4]);
            *reinterpret_cast<float4*>(
                &g_GsT[((size_t)bb * 512 + sg * 128 + n) * 128 + o4]) = v;
        }
    } else {
        #pragma unroll
        for (int mt = 0; mt < 4; mt++) {
            int o_lo = wm * 64 + mt * 16 + g;
            int o_hi = o_lo + 8;
            float b_lo = eb[o_lo], g_lo = eg[o_lo], t_lo = ebt[o_lo];
            float b_hi = eb[o_hi], g_hi = eg[o_hi], t_hi = ebt[o_hi];
            #pragma unroll
            for (int nt = 0; nt < 4; nt++) {
                int n = ng * 128 + wn * 32 + nt * 8 + 2 * t4;
                float2 v0, v1;
                v0.x = bn_gelu(d[mt][nt][0] + b_lo, g_lo, t_lo);
                v0.y = bn_gelu(d[mt][nt][1] + b_lo, g_lo, t_lo);
                v1.x = bn_gelu(d[mt][nt][2] + b_hi, g_hi, t_hi);
                v1.y = bn_gelu(d[mt][nt][3] + b_hi, g_hi, t_hi);
                *reinterpret_cast<float2*>(&Cout[((size_t)bb * 128 + o_lo) * 256 + n]) = v0;
                *reinterpret_cast<float2*>(&Cout[((size_t)bb * 128 + o_hi) * 256 + n]) = v1;
            }
        }
    }
}

// ---------------------------------------------------------------------------
// d4 paired-p (unchanged from R7)
// ---------------------------------------------------------------------------
__global__ __launch_bounds__(256) void k_d4(const float* __restrict__ dn_b,
                                            const float* __restrict__ dn_g,
                                            const float* __restrict__ dn_beta) {
    int tid = blockIdx.x * 256 + threadIdx.x;
    int i = (tid & 31) * 4;
    int p = (tid >> 5) & 15;
    int m = (tid >> 9) & 15;
    int b = tid >> 13;
    int ctr = g_fps[b * M_CTR + m];
    int i0 = g_knn[(b * M_CTR + m) * 2 + 0];
    int i1 = g_knn[(b * M_CTR + m) * 2 + 1];
    float4 bb = *reinterpret_cast<const float4*>(&dn_b[i]);
    float4 gg = *reinterpret_cast<const float4*>(&dn_g[i]);
    float4 bt = *reinterpret_cast<const float4*>(&dn_beta[i]);
    const float* Gb = g_GsT + (size_t)b * 512 * 128;
    float4 gc = *reinterpret_cast<const float4*>(&Gb[(size_t)(ctr * 16 + p) * 128 + i]);
    float4 x0 = *reinterpret_cast<const float4*>(&Gb[(size_t)(i0 * 16 + p) * 128 + i]);
    float4 x1 = *reinterpret_cast<const float4*>(&Gb[(size_t)(i1 * 16 + p) * 128 + i]);
    float4 va, vb2;
    va.x = fmaxf(bn_gelu(x0.x - gc.x + bb.x, gg.x, bt.x), bn_gelu(x1.x - gc.x + bb.x, gg.x, bt.x));
    va.y = fmaxf(bn_gelu(x0.y - gc.y + bb.y, gg.y, bt.y), bn_gelu(x1.y - gc.y + bb.y, gg.y, bt.y));
    va.z = fmaxf(bn_gelu(x0.z - gc.z + bb.z, gg.z, bt.z), bn_gelu(x1.z - gc.z + bb.z, gg.z, bt.z));
    va.w = fmaxf(bn_gelu(x0.w - gc.w + bb.w, gg.w, bt.w), bn_gelu(x1.w - gc.w + bb.w, gg.w, bt.w));
    vb2.x = bn_gelu(gc.x + bb.x, gg.x, bt.x);
    vb2.y = bn_gelu(gc.y + bb.y, gg.y, bt.y);
    vb2.z = bn_gelu(gc.z + bb.z, gg.z, bt.z);
    vb2.w = bn_gelu(gc.w + bb.w, gg.w, bt.w);
    float* outp = g_d4m + (((size_t)b * 16 + m) * 32 + p) * 128 + i;
    *reinterpret_cast<float4*>(outp) = va;
    *reinterpret_cast<float4*>(outp + 16 * 128) = vb2;
}

// ---------------------------------------------------------------------------
extern "C" void kernel_launch(void* const* d_in, const int* in_sizes, int n_in,
                              void* d_out, int out_size) {
    const float* sparse_fea = (const float*)d_in[0];
    const float* dense_fea  = (const float*)d_in[1];
    const float* stk_coor   = (const float*)d_in[2];
    int base = 3;
    if (n_in >= 16 && in_sizes[3] == 1) base = 4;
    const float* sp_w    = (const float*)d_in[base + 0];
    const float* sp_b    = (const float*)d_in[base + 1];
    const float* sp_g    = (const float*)d_in[base + 2];
    const float* sp_beta = (const float*)d_in[base + 3];
    const float* dn_w    = (const float*)d_in[base + 4];
    const float* dn_b    = (const float*)d_in[base + 5];
    const float* dn_g    = (const float*)d_in[base + 6];
    const float* dn_beta = (const float*)d_in[base + 7];
    const float* ds_w    = (const float*)d_in[base + 8];
    const float* ds_b    = (const float*)d_in[base + 9];
    const float* ds_g    = (const float*)d_in[base + 10];
    const float* ds_beta = (const float*)d_in[base + 11];

    float* out = (float*)d_out;
    float* out_sparse = out;
    float* out_dense  = out + BS * 256 * M_CTR;
    float* out_coor   = out_dense + BS * 128 * M_CTR * 16;

    // raise dynamic smem limit for the dense big-tile kernel (67584 B)
    static bool attr_done = false;
    if (!attr_done) {
        cudaFuncSetAttribute(gemm_big<1>, cudaFuncAttributeMaxDynamicSharedMemorySize, 69632);
        cudaFuncSetAttribute(gemm_big<2>, cudaFuncAttributeMaxDynamicSharedMemorySize, 69632);
        attr_done = true;
    }

    k_fps_knn<<<BS, 32>>>(stk_coor, out_coor);
    gemm_sparse<<<dim3(64, 4), 256>>>(sp_w, sparse_fea, sp_b, sp_g, sp_beta, out_sparse);
    gemm_big<1><<<512, 256, 67584>>>(dn_w, dense_fea, nullptr, nullptr, nullptr, nullptr);
    k_d4<<<4096, 256>>>(dn_b, dn_g, dn_beta);
    gemm_big<2><<<256, 256, 32768>>>(ds_w, nullptr, ds_b, ds_g, ds_beta, out_dense);
}